// round 10
// baseline (speedup 1.0000x reference)
#include <cuda_runtime.h>
#include <cuda_bf16.h>
#include <math.h>
#include <stddef.h>
#include <stdint.h>

#define B_IMG 8192
#define PLANE_ELEMS (((size_t)B_IMG * 64 + 64) * 64)

// Persistent device buffers (module-load zero-init; never-written pads stay 0)
__device__ __nv_bfloat16 g_act1[((size_t)B_IMG * 256 + 64) * 64]; // [B*16*16+pad][64]
__device__ __nv_bfloat16 g_act2[2 * PLANE_ELEMS];                 // 2 planes [B*8*8+pad][64]
__device__ float         g_buf3[(size_t)B_IMG * 2304];            // [B][256*3*3]
__device__ __nv_bfloat16 g_w2T[9 * 128 * 64];                     // [s][oc][ic]
__device__ __nv_bfloat16 g_w3T[18 * 256 * 64];                    // [st][oc][ic_local]
__device__ float         g_bn2[256];                              // alpha[128], beta[128]
__device__ float         g_bn3[512];                              // alpha[256], beta[256]

__device__ __forceinline__ uint32_t smem_u32(const void* p) {
    uint32_t a;
    asm("{ .reg .u64 t; cvta.to.shared.u64 t, %1; cvt.u32.u64 %0, t; }" : "=r"(a) : "l"(p));
    return a;
}

#define LDSM_X4(R, addr) \
    asm volatile("ldmatrix.sync.aligned.m8n8.x4.shared.b16 {%0,%1,%2,%3}, [%4];" \
                 : "=r"((R)[0]), "=r"((R)[1]), "=r"((R)[2]), "=r"((R)[3]) : "r"(addr))

#define MMA16816(d, a, b0, b1) \
    asm volatile("mma.sync.aligned.m16n8k16.row.col.f32.bf16.bf16.f32 " \
                 "{%0,%1,%2,%3}, {%4,%5,%6,%7}, {%8,%9}, {%0,%1,%2,%3};" \
                 : "+f"((d)[0]), "+f"((d)[1]), "+f"((d)[2]), "+f"((d)[3]) \
                 : "r"((a)[0]), "r"((a)[1]), "r"((a)[2]), "r"((a)[3]), "r"(b0), "r"(b1))

#define CP16(sm, gp) \
    asm volatile("cp.async.cg.shared.global [%0], [%1], 16;" :: "r"((uint32_t)(sm)), "l"(gp))
#define CP_COMMIT() asm volatile("cp.async.commit_group;" ::: "memory")
#define CP_WAIT0()  asm volatile("cp.async.wait_group 0;" ::: "memory")
#define CP_WAIT1()  asm volatile("cp.async.wait_group 1;" ::: "memory")

// ---------------------------------------------------------------------------
// conv1 (FFMA): 1->64, 3x3 SAME, BN+ReLU+pool -> bf16 padded NHWC act1 (16x16)
// ---------------------------------------------------------------------------
__global__ __launch_bounds__(256) void conv1_kernel(
    const float* __restrict__ x, const float* __restrict__ w, const float* __restrict__ cb,
    const float* __restrict__ g, const float* __restrict__ bb,
    const float* __restrict__ m, const float* __restrict__ v)
{
    __shared__ float sIn[30 * 30];
    __shared__ float sW[64 * 9];
    __shared__ float sA[64];
    __shared__ float sB[64];
    int b = blockIdx.x, tid = threadIdx.x;

    for (int i = tid; i < 900; i += 256) sIn[i] = 0.f;
    for (int i = tid; i < 576; i += 256) sW[i] = w[i];
    if (tid < 64) {
        float a = g[tid] * rsqrtf(v[tid] + 1e-5f);
        sA[tid] = a;
        sB[tid] = (cb[tid] - m[tid]) * a + bb[tid];
    }
    __syncthreads();
    const float* xb = x + (size_t)b * 784;
    for (int i = tid; i < 784; i += 256) {
        int r = i / 28, c = i % 28;
        sIn[(r + 1) * 30 + c + 1] = xb[i];
    }
    __syncthreads();

    int oc = tid & 63;
    const float* wp = sW + oc * 9;
    float w0 = wp[0], w1 = wp[1], w2 = wp[2], w3 = wp[3], w4 = wp[4],
          w5 = wp[5], w6 = wp[6], w7 = wp[7], w8 = wp[8];
    float alpha = sA[oc], beta = sB[oc];
    __nv_bfloat16* ob = g_act1 + (size_t)b * 256 * 64;

    for (int idx = tid; idx < 196 * 64; idx += 256) {
        int pos = idx >> 6;
        int py = pos / 14, px = pos % 14;
        float best = -3.0e38f;
        #pragma unroll
        for (int dy = 0; dy < 2; dy++)
            #pragma unroll
            for (int dx = 0; dx < 2; dx++) {
                const float* pi = sIn + (2 * py + dy) * 30 + 2 * px + dx;
                float acc = w0 * pi[0] + w1 * pi[1] + w2 * pi[2]
                          + w3 * pi[30] + w4 * pi[31] + w5 * pi[32]
                          + w6 * pi[60] + w7 * pi[61] + w8 * pi[62];
                best = fmaxf(best, alpha * acc + beta);
            }
        ob[((py + 1) * 16 + px + 1) * 64 + oc] = __float2bfloat16(fmaxf(best, 0.f));
    }
}

// ---------------------------------------------------------------------------
// Weight transform + BN-affine precompute
// ---------------------------------------------------------------------------
__global__ __launch_bounds__(256) void wtrans_kernel(
    const float* __restrict__ w2, const float* __restrict__ w3,
    const float* __restrict__ cb2, const float* __restrict__ g2,
    const float* __restrict__ bb2, const float* __restrict__ m2,
    const float* __restrict__ v2,
    const float* __restrict__ cb3, const float* __restrict__ g3,
    const float* __restrict__ bb3, const float* __restrict__ m3,
    const float* __restrict__ v3)
{
    int i = blockIdx.x * 256 + threadIdx.x;
    if (i < 128) {
        float a = g2[i] * rsqrtf(v2[i] + 1e-5f);
        g_bn2[i] = a;
        g_bn2[128 + i] = (cb2[i] - m2[i]) * a + bb2[i];
    }
    if (i < 256) {
        float a = g3[i] * rsqrtf(v3[i] + 1e-5f);
        g_bn3[i] = a;
        g_bn3[256 + i] = (cb3[i] - m3[i]) * a + bb3[i];
    }
    if (i < 9 * 128 * 64) {
        int ic = i & 63, t = i >> 6;
        int oc = t & 127, s = t >> 7;
        g_w2T[i] = __float2bfloat16(w2[(oc * 64 + ic) * 9 + s]);
    }
    if (i < 18 * 256 * 64) {
        int icl = i & 63, t = i >> 6;
        int oc = t & 255, gi = t >> 8;      // gi = s9*2 + h
        int h = gi & 1, s9 = gi >> 1;
        g_w3T[i] = __float2bfloat16(w3[(oc * 128 + h * 64 + icl) * 9 + s9]);
    }
}

// ---------------------------------------------------------------------------
// conv2 HMMA (persistent): D[128oc x 256pos] per image, 9 shifts x K=64.
// XOR-swizzled 128B-pitch smem; weights resident; DOUBLE-BUFFERED act tiles
// (prefetch issued before the MMA loop). One syncthreads per image.
// ---------------------------------------------------------------------------
#define C2_SW_BYTES (9 * 128 * 128)              // 147456
#define C2_SB_OFF   C2_SW_BYTES
#define C2_SB_BYTES (264 * 128)                  // 33792 per buffer
#define C2_SMEM     (C2_SW_BYTES + 2 * C2_SB_BYTES) // 215040

__global__ __launch_bounds__(512, 1) void conv2_mma()
{
    extern __shared__ char dsm[];
    uint32_t sb = smem_u32(dsm);
    int tid = threadIdx.x;
    int lane = tid & 31, warp = tid >> 5;
    int wm = warp & 3, wn = warp >> 2;
    int t4 = lane & 3, trow = lane >> 2;

    // Weights -> swizzled smem: tile s at s*16384; row r pitch 128; unit q -> q^(r&7)
    for (int i = tid; i < 9216; i += 512) {
        uint4 val = ((const uint4*)g_w2T)[i];
        int rl = i >> 3, q = i & 7;
        int s = rl >> 7, r = rl & 127;
        *(uint4*)(dsm + s * 16384 + r * 128 + ((q ^ (r & 7)) << 4)) = val;
    }

    // BN affine per thread's 4 oc rows (precomputed)
    float al[2][2], be[2][2];
    #pragma unroll
    for (int i = 0; i < 2; i++)
        #pragma unroll
        for (int ro = 0; ro < 2; ro++) {
            int oc = wm * 32 + i * 16 + trow + ro * 8;
            al[i][ro] = g_bn2[oc];
            be[i][ro] = g_bn2[128 + oc];
        }

    int npairs = (wn == 3) ? 2 : 4;

    // Prefetch first image's act tile into buffer 0 (264 rows, swizzled)
    int img0 = blockIdx.x;
    if (img0 < B_IMG) {
        const char* src = (const char*)(g_act1 + (size_t)img0 * 256 * 64);
        for (int i = tid; i < 2112; i += 512) {
            int r = i >> 3, q = i & 7;
            CP16(sb + C2_SB_OFF + r * 128 + ((q ^ (r & 7)) << 4), src + i * 16);
        }
    }
    CP_COMMIT();
    __syncthreads();     // weights visible

    int pb = 0;
    for (int img = img0; img < B_IMG; img += gridDim.x) {
        CP_WAIT0();
        __syncthreads();                    // act tile pb ready for all

        // Prefetch next image into the other buffer (overlaps MMA + epilogue)
        int nxt = img + gridDim.x;
        if (nxt < B_IMG) {
            const char* src = (const char*)(g_act1 + (size_t)nxt * 256 * 64);
            uint32_t dstb = sb + C2_SB_OFF + (pb ^ 1) * C2_SB_BYTES;
            for (int i = tid; i < 2112; i += 512) {
                int r = i >> 3, q = i & 7;
                CP16(dstb + r * 128 + ((q ^ (r & 7)) << 4), src + i * 16);
            }
        }
        CP_COMMIT();

        float acc[2][8][4];
        #pragma unroll
        for (int i = 0; i < 2; i++)
            #pragma unroll
            for (int j = 0; j < 8; j++)
                #pragma unroll
                for (int k = 0; k < 4; k++) acc[i][j][k] = 0.f;

        uint32_t actb = sb + C2_SB_OFF + pb * C2_SB_BYTES;
        #pragma unroll 1
        for (int s = 0; s < 9; s++) {
            int shift = (s / 3) * 16 + (s % 3);
            uint32_t aB = sb + s * 16384;
            #pragma unroll
            for (int kt = 0; kt < 4; kt++) {
                int ua = kt * 2 + ((lane >> 4) & 1);   // A fragment k-unit
                int ub = kt * 2 + ((lane >> 3) & 1);   // B fragment k-unit (FIXED)
                uint32_t a[2][4];
                #pragma unroll
                for (int i = 0; i < 2; i++) {
                    int r = wm * 32 + i * 16 + (lane & 15);
                    LDSM_X4(a[i], aB + r * 128 + ((ua ^ (r & 7)) << 4));
                }
                #pragma unroll
                for (int jp = 0; jp < 4; jp++) {
                    if (jp < npairs) {
                        uint32_t r4[4];
                        int r = shift + wn * 64 + jp * 16 + ((lane & 16) >> 1) + (lane & 7);
                        LDSM_X4(r4, actb + r * 128 + ((ub ^ (r & 7)) << 4));
                        #pragma unroll
                        for (int i = 0; i < 2; i++) {
                            MMA16816(acc[i][2 * jp],     a[i], r4[0], r4[1]);
                            MMA16816(acc[i][2 * jp + 1], a[i], r4[2], r4[3]);
                        }
                    }
                }
            }
        }

        // Epilogue: BN + ReLU + 2x2 pool -> act2 interior
        #pragma unroll
        for (int i = 0; i < 2; i++)
            #pragma unroll
            for (int jj = 0; jj < 4; jj++) {
                int j = (jj < 2) ? jj : jj + 2;   // {0,1,4,5}
                int n0 = wn * 64 + j * 8 + 2 * t4;
                int p = n0 + 17;
                int r = p >> 4, c = p & 15;
                if ((r & 1) && r < 15 && (c & 1) && c < 15) {
                    #pragma unroll
                    for (int ro = 0; ro < 2; ro++) {
                        float a = al[i][ro], bt = be[i][ro];
                        float v0 = a * acc[i][j][2 * ro] + bt;
                        float v1 = a * acc[i][j][2 * ro + 1] + bt;
                        float v2 = a * acc[i][j + 2][2 * ro] + bt;
                        float v3 = a * acc[i][j + 2][2 * ro + 1] + bt;
                        float mx = fmaxf(fmaxf(fmaxf(v0, v1), fmaxf(v2, v3)), 0.f);
                        int oc = wm * 32 + i * 16 + trow + ro * 8;
                        int py = (r - 1) >> 1, px = (c - 1) >> 1;
                        g_act2[(size_t)(oc >> 6) * PLANE_ELEMS +
                               ((size_t)img * 64 + (py + 1) * 8 + px + 1) * 64 + (oc & 63)]
                            = __float2bfloat16(mx);
                    }
                }
            }
        pb ^= 1;
    }
}

// ---------------------------------------------------------------------------
// conv3 HMMA v3: 256 threads, 2 images x 128 oc per CTA, 2 CTAs/SM.
// 18 stages; A slices are PER-WARP private with a 2-deep cp.async ring ->
// NO block/named barriers in the mainloop (only __syncwarp).
// Epilogue: BN+ReLU+pool(6x6->3x3) -> fp32 g_buf3.
// ---------------------------------------------------------------------------
#define C3_B_WIN   9504                           // 66 rows * 144B
#define C3_A_OFF   (4 * C3_B_WIN)                 // 38016
#define C3_A_SLOT  4608                           // 32 rows * 144B
#define C3_SMEM    (C3_A_OFF + 8 * 2 * C3_A_SLOT) // 111744

__global__ __launch_bounds__(256, 2) void conv3_mma()
{
    extern __shared__ char dsm[];
    uint32_t sb = smem_u32(dsm);
    int tid = threadIdx.x;
    int lane = tid & 31, warp = tid >> 5;
    int wm = warp & 3, wn = warp >> 2;            // wn = local image (0/1)
    int t4 = lane & 3, trow = lane >> 2;
    int grp2 = blockIdx.x, half = blockIdx.y;

    // Per-warp A-slice prefetch for stage st into warp slot st&1
    auto prefA = [&](int st) {
        uint32_t dst = sb + C3_A_OFF + (uint32_t)(warp * 2 + (st & 1)) * C3_A_SLOT + lane * 144;
        const char* src = (const char*)g_w3T +
            (((size_t)st * 256 + half * 128 + wm * 32 + lane) * 64) * 2;
        #pragma unroll
        for (int q = 0; q < 8; q++)
            CP16(dst + q * 16, src + q * 16);
    };

    // B: 4 windows (2 images x 2 planes) of 66 rows each (144B pitch)
    for (int i = tid; i < 2112; i += 256) {
        int w = i / 528, rem = i - w * 528;
        int row = rem >> 3, q = rem & 7;
        int img = w >> 1, pl = w & 1;
        const char* src = (const char*)(g_act2 + (size_t)pl * PLANE_ELEMS +
                          ((size_t)(grp2 * 2 + img) * 64 + row) * 64 + q * 8);
        CP16(sb + (uint32_t)w * C3_B_WIN + row * 144 + q * 16, src);
    }
    prefA(0);
    CP_COMMIT();            // G0 = B + A0
    prefA(1);
    CP_COMMIT();            // G1 = A1
    CP_WAIT1();             // G0 complete
    __syncthreads();        // B + A0 visible to all

    float acc[2][6][4];
    #pragma unroll
    for (int i = 0; i < 2; i++)
        #pragma unroll
        for (int j = 0; j < 6; j++)
            #pragma unroll
            for (int k = 0; k < 4; k++) acc[i][j][k] = 0.f;

    #pragma unroll 1
    for (int st = 0; st < 18; st++) {
        int s9 = st >> 1, h = st & 1;
        int shift = (s9 / 3) * 8 + (s9 % 3);
        uint32_t aB = sb + C3_A_OFF + (uint32_t)(warp * 2 + (st & 1)) * C3_A_SLOT;
        uint32_t bB = sb + (uint32_t)(wn * 2 + h) * C3_B_WIN + shift * 144;
        #pragma unroll
        for (int kt = 0; kt < 4; kt++) {
            uint32_t a[2][4];
            #pragma unroll
            for (int i = 0; i < 2; i++) {
                uint32_t addr = aB + (i * 16 + (lane & 15)) * 144 + ((lane >> 4) & 1) * 16 + kt * 32;
                LDSM_X4(a[i], addr);
            }
            #pragma unroll
            for (int jp = 0; jp < 3; jp++) {
                uint32_t r[4];
                uint32_t addr = bB + (jp * 16 + ((lane & 16) >> 1) + (lane & 7)) * 144
                                + kt * 32 + ((lane >> 3) & 1) * 16;
                LDSM_X4(r, addr);
                #pragma unroll
                for (int i = 0; i < 2; i++) {
                    MMA16816(acc[i][2 * jp],     a[i], r[0], r[1]);
                    MMA16816(acc[i][2 * jp + 1], a[i], r[2], r[3]);
                }
            }
        }
        // Warp-local ring advance: slot (st&1) fully consumed above.
        if (st + 2 < 18) prefA(st + 2);
        CP_COMMIT();
        CP_WAIT1();                                // A(st+1) landed (thread-local)
        __syncwarp();                              // cross-lane visibility
    }

    // Epilogue: BN + ReLU + pool -> g_buf3 (precomputed affine)
    int img = grp2 * 2 + wn;
    #pragma unroll
    for (int i = 0; i < 2; i++)
        #pragma unroll
        for (int ro = 0; ro < 2; ro++) {
            int ch = half * 128 + wm * 32 + i * 16 + trow + ro * 8;
            float a = g_bn3[ch];
            float bt = g_bn3[256 + ch];
            if (t4 < 3) {
                #pragma unroll
                for (int jh = 0; jh < 3; jh++) {
                    int j = 2 * jh;
                    float v0 = a * acc[i][j][2 * ro] + bt;
                    float v1 = a * acc[i][j][2 * ro + 1] + bt;
                    float v2 = a * acc[i][j + 1][2 * ro] + bt;
                    float v3 = a * acc[i][j + 1][2 * ro + 1] + bt;
                    float mx = fmaxf(fmaxf(fmaxf(v0, v1), fmaxf(v2, v3)), 0.f);
                    g_buf3[(size_t)img * 2304 + ch * 9 + jh * 3 + t4] = mx;
                }
            }
        }
}

// ---------------------------------------------------------------------------
// Tail: analytic quantum collapse + fc chain + log_softmax. 1 warp / image.
// ---------------------------------------------------------------------------
__global__ __launch_bounds__(256) void tail_kernel(
    const float* __restrict__ fc1_w, const float* __restrict__ fc1_b,
    const float* __restrict__ qp,
    const float* __restrict__ fc2_w, const float* __restrict__ fc2_b,
    const float* __restrict__ fc3_w, const float* __restrict__ fc3_b,
    float* __restrict__ out)
{
    __shared__ float sAC[4];
    int tid = threadIdx.x;
    if (tid == 0) {
        float a0 = 0.f, a1 = 0.f, c0 = 0.f, c1 = 0.f;
        for (int j = 0; j < 128; j++) {
            float f2 = fc2_w[j], f2b = fc2_b[j];
            a0 += fc3_w[j] * f2;       a1 += fc3_w[128 + j] * f2;
            c0 += fc3_w[j] * f2b;      c1 += fc3_w[128 + j] * f2b;
        }
        sAC[0] = a0; sAC[1] = a1;
        sAC[2] = c0 + fc3_b[0]; sAC[3] = c1 + fc3_b[1];
    }
    __syncthreads();

    int warp = tid >> 5, lane = tid & 31;
    int b = blockIdx.x * 8 + warp;
    const float* p3 = g_buf3 + (size_t)b * 2304;
    const float* w1 = fc1_w + 2304;
    float s = 0.f;
    for (int i = lane; i < 2304; i += 32) s += p3[i] * w1[i];
    #pragma unroll
    for (int o = 16; o; o >>= 1) s += __shfl_xor_sync(0xffffffffu, s, o);
    if (lane == 0) {
        s += fc1_b[1];
        float q = cosf(s) * cosf(qp[1]);
        float l0 = q * sAC[0] + sAC[2];
        float l1 = q * sAC[1] + sAC[3];
        float mx = fmaxf(l0, l1);
        float lse = mx + logf(expf(l0 - mx) + expf(l1 - mx));
        out[(size_t)b * 2]     = l0 - lse;
        out[(size_t)b * 2 + 1] = l1 - lse;
    }
}

// ---------------------------------------------------------------------------
extern "C" void kernel_launch(void* const* d_in, const int* in_sizes, int n_in,
                              void* d_out, int out_size)
{
    const float* x    = (const float*)d_in[0];
    const float* c1w  = (const float*)d_in[1];
    const float* c1b  = (const float*)d_in[2];
    const float* c2w  = (const float*)d_in[3];
    const float* c2b  = (const float*)d_in[4];
    const float* c3w  = (const float*)d_in[5];
    const float* c3b  = (const float*)d_in[6];
    const float* bn1g = (const float*)d_in[7];
    const float* bn1b = (const float*)d_in[8];
    const float* bn1m = (const float*)d_in[9];
    const float* bn1v = (const float*)d_in[10];
    const float* bn2g = (const float*)d_in[11];
    const float* bn2b = (const float*)d_in[12];
    const float* bn2m = (const float*)d_in[13];
    const float* bn2v = (const float*)d_in[14];
    const float* bn3g = (const float*)d_in[15];
    const float* bn3b = (const float*)d_in[16];
    const float* bn3m = (const float*)d_in[17];
    const float* bn3v = (const float*)d_in[18];
    const float* fc1w = (const float*)d_in[19];
    const float* fc1b = (const float*)d_in[20];
    const float* qpar = (const float*)d_in[21];
    const float* fc2w = (const float*)d_in[22];
    const float* fc2b = (const float*)d_in[23];
    const float* fc3w = (const float*)d_in[24];
    const float* fc3b = (const float*)d_in[25];
    float* out = (float*)d_out;

    cudaFuncSetAttribute(conv2_mma, cudaFuncAttributeMaxDynamicSharedMemorySize, C2_SMEM);
    cudaFuncSetAttribute(conv3_mma, cudaFuncAttributeMaxDynamicSharedMemorySize, C3_SMEM);

    conv1_kernel<<<B_IMG, 256>>>(x, c1w, c1b, bn1g, bn1b, bn1m, bn1v);
    wtrans_kernel<<<(18 * 256 * 64 + 255) / 256, 256>>>(
        c2w, c3w, c2b, bn2g, bn2b, bn2m, bn2v, c3b, bn3g, bn3b, bn3m, bn3v);
    conv2_mma<<<592, 512, C2_SMEM>>>();
    conv3_mma<<<dim3(B_IMG / 2, 2), 256, C3_SMEM>>>();
    tail_kernel<<<B_IMG / 8, 256>>>(fc1w, fc1b, qpar, fc2w, fc2b, fc3w, fc3b, out);
}

// round 11
// speedup vs baseline: 1.4294x; 1.4294x over previous
#include <cuda_runtime.h>
#include <cuda_bf16.h>
#include <math.h>
#include <stddef.h>
#include <stdint.h>

#define B_IMG 8192
#define PLANE_ELEMS (((size_t)B_IMG * 64 + 64) * 64)

// Persistent device buffers (module-load zero-init; never-written pads stay 0)
__device__ __nv_bfloat16 g_act1[((size_t)B_IMG * 256 + 64) * 64]; // [B*16*16+pad][64]
__device__ __nv_bfloat16 g_act2[2 * PLANE_ELEMS];                 // 2 planes [B*8*8+pad][64]
__device__ float         g_buf3[(size_t)B_IMG * 2304];            // [B][256*3*3]
__device__ __nv_bfloat16 g_w2T[9 * 128 * 64];                     // [s][oc][ic]
__device__ __nv_bfloat16 g_w3T[18 * 256 * 64];                    // [st][oc][ic_local]
__device__ float         g_bn2[256];                              // alpha[128], beta[128]
__device__ float         g_bn3[512];                              // alpha[256], beta[256]

__device__ __forceinline__ uint32_t smem_u32(const void* p) {
    uint32_t a;
    asm("{ .reg .u64 t; cvta.to.shared.u64 t, %1; cvt.u32.u64 %0, t; }" : "=r"(a) : "l"(p));
    return a;
}

#define LDSM_X4(R, addr) \
    asm volatile("ldmatrix.sync.aligned.m8n8.x4.shared.b16 {%0,%1,%2,%3}, [%4];" \
                 : "=r"((R)[0]), "=r"((R)[1]), "=r"((R)[2]), "=r"((R)[3]) : "r"(addr))

#define MMA16816(d, a, b0, b1) \
    asm volatile("mma.sync.aligned.m16n8k16.row.col.f32.bf16.bf16.f32 " \
                 "{%0,%1,%2,%3}, {%4,%5,%6,%7}, {%8,%9}, {%0,%1,%2,%3};" \
                 : "+f"((d)[0]), "+f"((d)[1]), "+f"((d)[2]), "+f"((d)[3]) \
                 : "r"((a)[0]), "r"((a)[1]), "r"((a)[2]), "r"((a)[3]), "r"(b0), "r"(b1))

#define CP16(sm, gp) \
    asm volatile("cp.async.cg.shared.global [%0], [%1], 16;" :: "r"((uint32_t)(sm)), "l"(gp))
#define CP_COMMIT() asm volatile("cp.async.commit_group;" ::: "memory")
#define CP_WAIT0()  asm volatile("cp.async.wait_group 0;" ::: "memory")
#define CP_WAIT1()  asm volatile("cp.async.wait_group 1;" ::: "memory")
#define BAR_GRP(id, n) asm volatile("bar.sync %0, %1;" :: "r"(id), "r"(n) : "memory")

// ---------------------------------------------------------------------------
// conv1 (FFMA): 1->64, 3x3 SAME, BN+ReLU+pool -> bf16 padded NHWC act1 (16x16)
// ---------------------------------------------------------------------------
__global__ __launch_bounds__(256) void conv1_kernel(
    const float* __restrict__ x, const float* __restrict__ w, const float* __restrict__ cb,
    const float* __restrict__ g, const float* __restrict__ bb,
    const float* __restrict__ m, const float* __restrict__ v)
{
    __shared__ float sIn[30 * 30];
    __shared__ float sW[64 * 9];
    __shared__ float sA[64];
    __shared__ float sB[64];
    int b = blockIdx.x, tid = threadIdx.x;

    for (int i = tid; i < 900; i += 256) sIn[i] = 0.f;
    for (int i = tid; i < 576; i += 256) sW[i] = w[i];
    if (tid < 64) {
        float a = g[tid] * rsqrtf(v[tid] + 1e-5f);
        sA[tid] = a;
        sB[tid] = (cb[tid] - m[tid]) * a + bb[tid];
    }
    __syncthreads();
    const float* xb = x + (size_t)b * 784;
    for (int i = tid; i < 784; i += 256) {
        int r = i / 28, c = i % 28;
        sIn[(r + 1) * 30 + c + 1] = xb[i];
    }
    __syncthreads();

    int oc = tid & 63;
    const float* wp = sW + oc * 9;
    float w0 = wp[0], w1 = wp[1], w2 = wp[2], w3 = wp[3], w4 = wp[4],
          w5 = wp[5], w6 = wp[6], w7 = wp[7], w8 = wp[8];
    float alpha = sA[oc], beta = sB[oc];
    __nv_bfloat16* ob = g_act1 + (size_t)b * 256 * 64;

    for (int idx = tid; idx < 196 * 64; idx += 256) {
        int pos = idx >> 6;
        int py = pos / 14, px = pos % 14;
        float best = -3.0e38f;
        #pragma unroll
        for (int dy = 0; dy < 2; dy++)
            #pragma unroll
            for (int dx = 0; dx < 2; dx++) {
                const float* pi = sIn + (2 * py + dy) * 30 + 2 * px + dx;
                float acc = w0 * pi[0] + w1 * pi[1] + w2 * pi[2]
                          + w3 * pi[30] + w4 * pi[31] + w5 * pi[32]
                          + w6 * pi[60] + w7 * pi[61] + w8 * pi[62];
                best = fmaxf(best, alpha * acc + beta);
            }
        ob[((py + 1) * 16 + px + 1) * 64 + oc] = __float2bfloat16(fmaxf(best, 0.f));
    }
}

// ---------------------------------------------------------------------------
// Weight transform + BN-affine precompute
// ---------------------------------------------------------------------------
__global__ __launch_bounds__(256) void wtrans_kernel(
    const float* __restrict__ w2, const float* __restrict__ w3,
    const float* __restrict__ cb2, const float* __restrict__ g2,
    const float* __restrict__ bb2, const float* __restrict__ m2,
    const float* __restrict__ v2,
    const float* __restrict__ cb3, const float* __restrict__ g3,
    const float* __restrict__ bb3, const float* __restrict__ m3,
    const float* __restrict__ v3)
{
    int i = blockIdx.x * 256 + threadIdx.x;
    if (i < 128) {
        float a = g2[i] * rsqrtf(v2[i] + 1e-5f);
        g_bn2[i] = a;
        g_bn2[128 + i] = (cb2[i] - m2[i]) * a + bb2[i];
    }
    if (i < 256) {
        float a = g3[i] * rsqrtf(v3[i] + 1e-5f);
        g_bn3[i] = a;
        g_bn3[256 + i] = (cb3[i] - m3[i]) * a + bb3[i];
    }
    if (i < 9 * 128 * 64) {
        int ic = i & 63, t = i >> 6;
        int oc = t & 127, s = t >> 7;
        g_w2T[i] = __float2bfloat16(w2[(oc * 64 + ic) * 9 + s]);
    }
    if (i < 18 * 256 * 64) {
        int icl = i & 63, t = i >> 6;
        int oc = t & 255, gi = t >> 8;      // gi = s9*2 + h
        int h = gi & 1, s9 = gi >> 1;
        g_w3T[i] = __float2bfloat16(w3[(oc * 128 + h * 64 + icl) * 9 + s9]);
    }
}

// ---------------------------------------------------------------------------
// conv2 HMMA (persistent): D[128oc x 256pos] per image, 9 shifts x K=64.
// XOR-swizzled 128B-pitch smem; weights resident; DOUBLE-BUFFERED act tiles.
// One syncthreads per image. (R7 version, ub selector fixed.)
// ---------------------------------------------------------------------------
#define C2_SW_BYTES (9 * 128 * 128)              // 147456
#define C2_SB_OFF   C2_SW_BYTES
#define C2_SB_BYTES (264 * 128)                  // 33792 per buffer
#define C2_SMEM     (C2_SW_BYTES + 2 * C2_SB_BYTES) // 215040

__global__ __launch_bounds__(512, 1) void conv2_mma()
{
    extern __shared__ char dsm[];
    uint32_t sb = smem_u32(dsm);
    int tid = threadIdx.x;
    int lane = tid & 31, warp = tid >> 5;
    int wm = warp & 3, wn = warp >> 2;
    int t4 = lane & 3, trow = lane >> 2;

    // Weights -> swizzled smem: tile s at s*16384; row r pitch 128; unit q -> q^(r&7)
    for (int i = tid; i < 9216; i += 512) {
        uint4 val = ((const uint4*)g_w2T)[i];
        int rl = i >> 3, q = i & 7;
        int s = rl >> 7, r = rl & 127;
        *(uint4*)(dsm + s * 16384 + r * 128 + ((q ^ (r & 7)) << 4)) = val;
    }

    float al[2][2], be[2][2];
    #pragma unroll
    for (int i = 0; i < 2; i++)
        #pragma unroll
        for (int ro = 0; ro < 2; ro++) {
            int oc = wm * 32 + i * 16 + trow + ro * 8;
            al[i][ro] = g_bn2[oc];
            be[i][ro] = g_bn2[128 + oc];
        }

    int npairs = (wn == 3) ? 2 : 4;

    int img0 = blockIdx.x;
    if (img0 < B_IMG) {
        const char* src = (const char*)(g_act1 + (size_t)img0 * 256 * 64);
        for (int i = tid; i < 2112; i += 512) {
            int r = i >> 3, q = i & 7;
            CP16(sb + C2_SB_OFF + r * 128 + ((q ^ (r & 7)) << 4), src + i * 16);
        }
    }
    CP_COMMIT();
    __syncthreads();     // weights visible

    int pb = 0;
    for (int img = img0; img < B_IMG; img += gridDim.x) {
        CP_WAIT0();
        __syncthreads();                    // act tile pb ready for all

        int nxt = img + gridDim.x;
        if (nxt < B_IMG) {
            const char* src = (const char*)(g_act1 + (size_t)nxt * 256 * 64);
            uint32_t dstb = sb + C2_SB_OFF + (pb ^ 1) * C2_SB_BYTES;
            for (int i = tid; i < 2112; i += 512) {
                int r = i >> 3, q = i & 7;
                CP16(dstb + r * 128 + ((q ^ (r & 7)) << 4), src + i * 16);
            }
        }
        CP_COMMIT();

        float acc[2][8][4];
        #pragma unroll
        for (int i = 0; i < 2; i++)
            #pragma unroll
            for (int j = 0; j < 8; j++)
                #pragma unroll
                for (int k = 0; k < 4; k++) acc[i][j][k] = 0.f;

        uint32_t actb = sb + C2_SB_OFF + pb * C2_SB_BYTES;
        #pragma unroll 1
        for (int s = 0; s < 9; s++) {
            int shift = (s / 3) * 16 + (s % 3);
            uint32_t aB = sb + s * 16384;
            #pragma unroll
            for (int kt = 0; kt < 4; kt++) {
                int ua = kt * 2 + ((lane >> 4) & 1);   // A fragment k-unit
                int ub = kt * 2 + ((lane >> 3) & 1);   // B fragment k-unit
                uint32_t a[2][4];
                #pragma unroll
                for (int i = 0; i < 2; i++) {
                    int r = wm * 32 + i * 16 + (lane & 15);
                    LDSM_X4(a[i], aB + r * 128 + ((ua ^ (r & 7)) << 4));
                }
                #pragma unroll
                for (int jp = 0; jp < 4; jp++) {
                    if (jp < npairs) {
                        uint32_t r4[4];
                        int r = shift + wn * 64 + jp * 16 + ((lane & 16) >> 1) + (lane & 7);
                        LDSM_X4(r4, actb + r * 128 + ((ub ^ (r & 7)) << 4));
                        #pragma unroll
                        for (int i = 0; i < 2; i++) {
                            MMA16816(acc[i][2 * jp],     a[i], r4[0], r4[1]);
                            MMA16816(acc[i][2 * jp + 1], a[i], r4[2], r4[3]);
                        }
                    }
                }
            }
        }

        // Epilogue: BN + ReLU + 2x2 pool -> act2 interior
        #pragma unroll
        for (int i = 0; i < 2; i++)
            #pragma unroll
            for (int jj = 0; jj < 4; jj++) {
                int j = (jj < 2) ? jj : jj + 2;   // {0,1,4,5}
                int n0 = wn * 64 + j * 8 + 2 * t4;
                int p = n0 + 17;
                int r = p >> 4, c = p & 15;
                if ((r & 1) && r < 15 && (c & 1) && c < 15) {
                    #pragma unroll
                    for (int ro = 0; ro < 2; ro++) {
                        float a = al[i][ro], bt = be[i][ro];
                        float v0 = a * acc[i][j][2 * ro] + bt;
                        float v1 = a * acc[i][j][2 * ro + 1] + bt;
                        float v2 = a * acc[i][j + 2][2 * ro] + bt;
                        float v3 = a * acc[i][j + 2][2 * ro + 1] + bt;
                        float mx = fmaxf(fmaxf(fmaxf(v0, v1), fmaxf(v2, v3)), 0.f);
                        int oc = wm * 32 + i * 16 + trow + ro * 8;
                        int py = (r - 1) >> 1, px = (c - 1) >> 1;
                        g_act2[(size_t)(oc >> 6) * PLANE_ELEMS +
                               ((size_t)img * 64 + (py + 1) * 8 + px + 1) * 64 + (oc & 63)]
                            = __float2bfloat16(mx);
                    }
                }
            }
        pb ^= 1;
    }
}

// ---------------------------------------------------------------------------
// conv3 HMMA (R5 revert): 256 threads, 2 images x 128 oc per CTA, 2 CTAs/SM.
// 18 stages; A slices stream via wm-group-shared 3-deep cp.async ring with
// 64-thread named barriers (one load per slice, two consumer warps).
// Dead n8-tiles skipped (jp 0..2). Epilogue: BN+ReLU+pool -> fp32 g_buf3.
// ---------------------------------------------------------------------------
#define C3_B_WIN   9504                           // 66 rows * 144B
#define C3_A_OFF   (4 * C3_B_WIN)                 // 38016
#define C3_A_STAGE 4608                           // 32 rows * 144B
#define C3_SMEM    (C3_A_OFF + 4 * 3 * C3_A_STAGE) // 93312

__global__ __launch_bounds__(256, 2) void conv3_mma()
{
    extern __shared__ char dsm[];
    uint32_t sb = smem_u32(dsm);
    int tid = threadIdx.x;
    int lane = tid & 31, warp = tid >> 5;
    int wm = warp & 3, wn = warp >> 2;            // wn = local image (0/1)
    int t4 = lane & 3, trow = lane >> 2;
    int grp2 = blockIdx.x, half = blockIdx.y;
    int gi = wn * 32 + lane;                      // 0..63 within wm-group

    // A-slice prefetch for stage st into ring slot st%3 (wm-group shared)
    auto prefA = [&](int st) {
        uint32_t dst0 = sb + C3_A_OFF + (uint32_t)(wm * 3 + (st % 3)) * C3_A_STAGE;
        #pragma unroll
        for (int u = 0; u < 4; u++) {
            int idx = gi + u * 64;                // 0..255
            int row = idx >> 3, q = idx & 7;
            const char* src = (const char*)g_w3T +
                (((size_t)st * 256 + half * 128 + wm * 32 + row) * 64 + q * 8) * 2;
            CP16(dst0 + row * 144 + q * 16, src);
        }
    };

    // B: 4 windows (2 images x 2 planes) of 66 rows each (144B pitch)
    for (int i = tid; i < 2112; i += 256) {
        int w = i / 528, rem = i - w * 528;
        int row = rem >> 3, q = rem & 7;
        int img = w >> 1, pl = w & 1;
        const char* src = (const char*)(g_act2 + (size_t)pl * PLANE_ELEMS +
                          ((size_t)(grp2 * 2 + img) * 64 + row) * 64 + q * 8);
        CP16(sb + (uint32_t)w * C3_B_WIN + row * 144 + q * 16, src);
    }
    prefA(0);
    CP_COMMIT();            // G0 = B + A0
    prefA(1);
    CP_COMMIT();            // G1 = A1
    CP_WAIT1();             // G0 complete
    __syncthreads();        // B + A0 visible to all

    float acc[2][6][4];
    #pragma unroll
    for (int i = 0; i < 2; i++)
        #pragma unroll
        for (int j = 0; j < 6; j++)
            #pragma unroll
            for (int k = 0; k < 4; k++) acc[i][j][k] = 0.f;

    #pragma unroll 1
    for (int st = 0; st < 18; st++) {
        if (st + 2 < 18) prefA(st + 2);
        CP_COMMIT();                               // uniform group numbering

        int s9 = st >> 1, h = st & 1;
        int shift = (s9 / 3) * 8 + (s9 % 3);
        uint32_t aB = sb + C3_A_OFF + (uint32_t)(wm * 3 + (st % 3)) * C3_A_STAGE;
        uint32_t bB = sb + (uint32_t)(wn * 2 + h) * C3_B_WIN + shift * 144;
        #pragma unroll
        for (int kt = 0; kt < 4; kt++) {
            uint32_t a[2][4];
            #pragma unroll
            for (int i = 0; i < 2; i++) {
                uint32_t addr = aB + (i * 16 + (lane & 15)) * 144 + ((lane >> 4) & 1) * 16 + kt * 32;
                LDSM_X4(a[i], addr);
            }
            #pragma unroll
            for (int jp = 0; jp < 3; jp++) {
                uint32_t r[4];
                uint32_t addr = bB + (jp * 16 + ((lane & 16) >> 1) + (lane & 7)) * 144
                                + kt * 32 + ((lane >> 3) & 1) * 16;
                LDSM_X4(r, addr);
                #pragma unroll
                for (int i = 0; i < 2; i++) {
                    MMA16816(acc[i][2 * jp],     a[i], r[0], r[1]);
                    MMA16816(acc[i][2 * jp + 1], a[i], r[2], r[3]);
                }
            }
        }
        CP_WAIT1();                                // A(st+1) complete
        BAR_GRP(1 + wm, 64);                       // group-local visibility + ring safety
    }

    // Epilogue: BN + ReLU + pool -> g_buf3 (precomputed affine)
    int img = grp2 * 2 + wn;
    #pragma unroll
    for (int i = 0; i < 2; i++)
        #pragma unroll
        for (int ro = 0; ro < 2; ro++) {
            int ch = half * 128 + wm * 32 + i * 16 + trow + ro * 8;
            float a = g_bn3[ch];
            float bt = g_bn3[256 + ch];
            if (t4 < 3) {
                #pragma unroll
                for (int jh = 0; jh < 3; jh++) {
                    int j = 2 * jh;
                    float v0 = a * acc[i][j][2 * ro] + bt;
                    float v1 = a * acc[i][j][2 * ro + 1] + bt;
                    float v2 = a * acc[i][j + 1][2 * ro] + bt;
                    float v3 = a * acc[i][j + 1][2 * ro + 1] + bt;
                    float mx = fmaxf(fmaxf(fmaxf(v0, v1), fmaxf(v2, v3)), 0.f);
                    g_buf3[(size_t)img * 2304 + ch * 9 + jh * 3 + t4] = mx;
                }
            }
        }
}

// ---------------------------------------------------------------------------
// Tail: analytic quantum collapse + fc chain + log_softmax. 1 warp / image.
// ---------------------------------------------------------------------------
__global__ __launch_bounds__(256) void tail_kernel(
    const float* __restrict__ fc1_w, const float* __restrict__ fc1_b,
    const float* __restrict__ qp,
    const float* __restrict__ fc2_w, const float* __restrict__ fc2_b,
    const float* __restrict__ fc3_w, const float* __restrict__ fc3_b,
    float* __restrict__ out)
{
    __shared__ float sAC[4];
    int tid = threadIdx.x;
    if (tid == 0) {
        float a0 = 0.f, a1 = 0.f, c0 = 0.f, c1 = 0.f;
        for (int j = 0; j < 128; j++) {
            float f2 = fc2_w[j], f2b = fc2_b[j];
            a0 += fc3_w[j] * f2;       a1 += fc3_w[128 + j] * f2;
            c0 += fc3_w[j] * f2b;      c1 += fc3_w[128 + j] * f2b;
        }
        sAC[0] = a0; sAC[1] = a1;
        sAC[2] = c0 + fc3_b[0]; sAC[3] = c1 + fc3_b[1];
    }
    __syncthreads();

    int warp = tid >> 5, lane = tid & 31;
    int b = blockIdx.x * 8 + warp;
    const float* p3 = g_buf3 + (size_t)b * 2304;
    const float* w1 = fc1_w + 2304;
    float s = 0.f;
    for (int i = lane; i < 2304; i += 32) s += p3[i] * w1[i];
    #pragma unroll
    for (int o = 16; o; o >>= 1) s += __shfl_xor_sync(0xffffffffu, s, o);
    if (lane == 0) {
        s += fc1_b[1];
        float q = cosf(s) * cosf(qp[1]);
        float l0 = q * sAC[0] + sAC[2];
        float l1 = q * sAC[1] + sAC[3];
        float mx = fmaxf(l0, l1);
        float lse = mx + logf(expf(l0 - mx) + expf(l1 - mx));
        out[(size_t)b * 2]     = l0 - lse;
        out[(size_t)b * 2 + 1] = l1 - lse;
    }
}

// ---------------------------------------------------------------------------
extern "C" void kernel_launch(void* const* d_in, const int* in_sizes, int n_in,
                              void* d_out, int out_size)
{
    const float* x    = (const float*)d_in[0];
    const float* c1w  = (const float*)d_in[1];
    const float* c1b  = (const float*)d_in[2];
    const float* c2w  = (const float*)d_in[3];
    const float* c2b  = (const float*)d_in[4];
    const float* c3w  = (const float*)d_in[5];
    const float* c3b  = (const float*)d_in[6];
    const float* bn1g = (const float*)d_in[7];
    const float* bn1b = (const float*)d_in[8];
    const float* bn1m = (const float*)d_in[9];
    const float* bn1v = (const float*)d_in[10];
    const float* bn2g = (const float*)d_in[11];
    const float* bn2b = (const float*)d_in[12];
    const float* bn2m = (const float*)d_in[13];
    const float* bn2v = (const float*)d_in[14];
    const float* bn3g = (const float*)d_in[15];
    const float* bn3b = (const float*)d_in[16];
    const float* bn3m = (const float*)d_in[17];
    const float* bn3v = (const float*)d_in[18];
    const float* fc1w = (const float*)d_in[19];
    const float* fc1b = (const float*)d_in[20];
    const float* qpar = (const float*)d_in[21];
    const float* fc2w = (const float*)d_in[22];
    const float* fc2b = (const float*)d_in[23];
    const float* fc3w = (const float*)d_in[24];
    const float* fc3b = (const float*)d_in[25];
    float* out = (float*)d_out;

    cudaFuncSetAttribute(conv2_mma, cudaFuncAttributeMaxDynamicSharedMemorySize, C2_SMEM);
    cudaFuncSetAttribute(conv3_mma, cudaFuncAttributeMaxDynamicSharedMemorySize, C3_SMEM);

    conv1_kernel<<<B_IMG, 256>>>(x, c1w, c1b, bn1g, bn1b, bn1m, bn1v);
    wtrans_kernel<<<(18 * 256 * 64 + 255) / 256, 256>>>(
        c2w, c3w, c2b, bn2g, bn2b, bn2m, bn2v, c3b, bn3g, bn3b, bn3m, bn3v);
    conv2_mma<<<592, 512, C2_SMEM>>>();
    conv3_mma<<<dim3(B_IMG / 2, 2), 256, C3_SMEM>>>();
    tail_kernel<<<B_IMG / 8, 256>>>(fc1w, fc1b, qpar, fc2w, fc2b, fc3w, fc3b, out);
}

// round 16
// speedup vs baseline: 1.5278x; 1.0688x over previous
#include <cuda_runtime.h>
#include <cuda_bf16.h>
#include <math.h>
#include <stddef.h>
#include <stdint.h>

#define B_IMG 8192
#define PLANE_ELEMS (((size_t)B_IMG * 64 + 64) * 64)

// Persistent device buffers (module-load zero-init; never-written pads stay 0)
__device__ __nv_bfloat16 g_act1[((size_t)B_IMG * 256 + 64) * 64]; // [B*16*16+pad][64]
__device__ __nv_bfloat16 g_act2[2 * PLANE_ELEMS];                 // 2 planes [B*8*8+pad][64]
__device__ float         g_buf3[(size_t)B_IMG * 2304];            // [B][256*3*3]
__device__ __align__(16) __nv_bfloat16 g_w1T[64 * 16];            // [oc][tap(9)+pad]
__device__ __nv_bfloat16 g_w2T[9 * 128 * 64];                     // [s][oc][ic]
__device__ __nv_bfloat16 g_w3T[18 * 256 * 64];                    // [st][oc][ic_local]
__device__ float         g_bn1[128];                              // alpha[64], beta[64]
__device__ float         g_bn2[256];                              // alpha[128], beta[128]
__device__ float         g_bn3[512];                              // alpha[256], beta[256]

__device__ __forceinline__ uint32_t smem_u32(const void* p) {
    uint32_t a;
    asm("{ .reg .u64 t; cvta.to.shared.u64 t, %1; cvt.u32.u64 %0, t; }" : "=r"(a) : "l"(p));
    return a;
}

#define LDSM_X4(R, addr) \
    asm volatile("ldmatrix.sync.aligned.m8n8.x4.shared.b16 {%0,%1,%2,%3}, [%4];" \
                 : "=r"((R)[0]), "=r"((R)[1]), "=r"((R)[2]), "=r"((R)[3]) : "r"(addr))

#define MMA16816(d, a, b0, b1) \
    asm volatile("mma.sync.aligned.m16n8k16.row.col.f32.bf16.bf16.f32 " \
                 "{%0,%1,%2,%3}, {%4,%5,%6,%7}, {%8,%9}, {%0,%1,%2,%3};" \
                 : "+f"((d)[0]), "+f"((d)[1]), "+f"((d)[2]), "+f"((d)[3]) \
                 : "r"((a)[0]), "r"((a)[1]), "r"((a)[2]), "r"((a)[3]), "r"(b0), "r"(b1))

#define CP16(sm, gp) \
    asm volatile("cp.async.cg.shared.global [%0], [%1], 16;" :: "r"((uint32_t)(sm)), "l"(gp))
#define CP_COMMIT() asm volatile("cp.async.commit_group;" ::: "memory")
#define CP_WAIT0()  asm volatile("cp.async.wait_group 0;" ::: "memory")
#define CP_WAIT1()  asm volatile("cp.async.wait_group 1;" ::: "memory")
#define BAR_GRP(id, n) asm volatile("bar.sync %0, %1;" :: "r"(id), "r"(n) : "memory")

// ---------------------------------------------------------------------------
// Weight transform + BN-affine precompute (includes conv1)
// ---------------------------------------------------------------------------
__global__ __launch_bounds__(256) void wtrans_kernel(
    const float* __restrict__ w1,
    const float* __restrict__ w2, const float* __restrict__ w3,
    const float* __restrict__ cb1, const float* __restrict__ g1,
    const float* __restrict__ bb1, const float* __restrict__ m1,
    const float* __restrict__ v1,
    const float* __restrict__ cb2, const float* __restrict__ g2,
    const float* __restrict__ bb2, const float* __restrict__ m2,
    const float* __restrict__ v2,
    const float* __restrict__ cb3, const float* __restrict__ g3,
    const float* __restrict__ bb3, const float* __restrict__ m3,
    const float* __restrict__ v3)
{
    int i = blockIdx.x * 256 + threadIdx.x;
    if (i < 64) {
        float a = g1[i] * rsqrtf(v1[i] + 1e-5f);
        g_bn1[i] = a;
        g_bn1[64 + i] = (cb1[i] - m1[i]) * a + bb1[i];
    }
    if (i < 128) {
        float a = g2[i] * rsqrtf(v2[i] + 1e-5f);
        g_bn2[i] = a;
        g_bn2[128 + i] = (cb2[i] - m2[i]) * a + bb2[i];
    }
    if (i < 256) {
        float a = g3[i] * rsqrtf(v3[i] + 1e-5f);
        g_bn3[i] = a;
        g_bn3[256 + i] = (cb3[i] - m3[i]) * a + bb3[i];
    }
    if (i < 1024) {
        int k = i & 15, oc = i >> 4;
        g_w1T[i] = __float2bfloat16(k < 9 ? w1[oc * 9 + k] : 0.f);
    }
    if (i < 9 * 128 * 64) {
        int ic = i & 63, t = i >> 6;
        int oc = t & 127, s = t >> 7;
        g_w2T[i] = __float2bfloat16(w2[(oc * 64 + ic) * 9 + s]);
    }
    if (i < 18 * 256 * 64) {
        int icl = i & 63, t = i >> 6;
        int oc = t & 255, gi = t >> 8;      // gi = s9*2 + h
        int h = gi & 1, s9 = gi >> 1;
        g_w3T[i] = __float2bfloat16(w3[(oc * 128 + h * 64 + icl) * 9 + s9]);
    }
}

// ---------------------------------------------------------------------------
// conv1 HMMA: im2col GEMM. M=64 oc, K=16 (9 taps + pad), N=784 in
// POOL-FRIENDLY order: n = 4*window + (dy*2+dx). One CTA per image.
// Epilogue: BN+ReLU+pool via one shfl_xor -> bf16 act1 interior.
// ALL smem buffers 16B-aligned (ldmatrix / vector-access requirement).
// ---------------------------------------------------------------------------
#define C1_PITCH 48
__global__ __launch_bounds__(256) void conv1_mma(const float* __restrict__ x)
{
    __shared__ __align__(16) __nv_bfloat16 sPad[30 * 30 + 4];   // padded to 16B multiple
    __shared__ __align__(16) char sA[64 * C1_PITCH];
    __shared__ __align__(16) char sB[784 * C1_PITCH];

    int b = blockIdx.x, tid = threadIdx.x;
    int lane = tid & 31, warp = tid >> 5;
    int t4 = lane & 3, trow = lane >> 2;

    // Padded 30x30 bf16 input
    for (int i = tid; i < 900; i += 256) sPad[i] = __float2bfloat16(0.f);
    __syncthreads();
    const float* xb = x + (size_t)b * 784;
    for (int i = tid; i < 784; i += 256) {
        int r = i / 28, c = i % 28;
        sPad[(r + 1) * 30 + c + 1] = __float2bfloat16(xb[i]);
    }
    // A tile: 64 rows x 16 bf16 (32B data, 48B pitch) — uint4 copy, both 16B-aligned
    if (tid < 64) {
        const uint4* srcA = (const uint4*)(g_w1T + tid * 16);
        uint4* dstA = (uint4*)(sA + tid * C1_PITCH);
        dstA[0] = srcA[0];
        dstA[1] = srcA[1];
    }
    __syncthreads();

    // B im2col: row n -> window w=n>>2, quad q=n&3 (dy=q>>1, dx=q&1)
    for (int n = tid; n < 784; n += 256) {
        int w = n >> 2, q = n & 3;
        int py = w / 14, px = w % 14;
        int r = 2 * py + (q >> 1), c = 2 * px + (q & 1);
        const uint16_t* p = (const uint16_t*)sPad + r * 30 + c;
        uint16_t tap[16];
        tap[0] = p[0];  tap[1] = p[1];  tap[2] = p[2];
        tap[3] = p[30]; tap[4] = p[31]; tap[5] = p[32];
        tap[6] = p[60]; tap[7] = p[61]; tap[8] = p[62];
        #pragma unroll
        for (int k = 9; k < 16; k++) tap[k] = 0;
        uint32_t* dst = (uint32_t*)(sB + n * C1_PITCH);
        #pragma unroll
        for (int q2 = 0; q2 < 8; q2++)
            dst[q2] = (uint32_t)tap[2 * q2] | ((uint32_t)tap[2 * q2 + 1] << 16);
    }
    __syncthreads();

    // BN affine per thread's 8 ocs
    float al[4][2], be[4][2];
    #pragma unroll
    for (int mi = 0; mi < 4; mi++)
        #pragma unroll
        for (int ro = 0; ro < 2; ro++) {
            int oc = mi * 16 + trow + ro * 8;
            al[mi][ro] = g_bn1[oc];
            be[mi][ro] = g_bn1[64 + oc];
        }

    // A fragments (all 4 m16 tiles, reused across n-tiles)
    uint32_t a[4][4];
    uint32_t aAddr = smem_u32(sA) + (lane & 15) * C1_PITCH + ((lane >> 4) & 1) * 16;
    #pragma unroll
    for (int mi = 0; mi < 4; mi++) LDSM_X4(a[mi], aAddr + mi * 16 * C1_PITCH);

    uint32_t sbB = smem_u32(sB);
    __nv_bfloat16* ob = g_act1 + (size_t)b * 256 * 64;

    // 49 n16 tiles round-robin across 8 warps
    for (int t = warp; t < 49; t += 8) {
        int nb = t * 16;
        uint32_t bf[4];
        LDSM_X4(bf, sbB + (uint32_t)(nb + ((lane & 16) >> 1) + (lane & 7)) * C1_PITCH
                     + ((lane >> 3) & 1) * 16);
        float acc[4][2][4];
        #pragma unroll
        for (int mi = 0; mi < 4; mi++) {
            #pragma unroll
            for (int nj = 0; nj < 2; nj++)
                #pragma unroll
                for (int k = 0; k < 4; k++) acc[mi][nj][k] = 0.f;
            MMA16816(acc[mi][0], a[mi], bf[0], bf[1]);
            MMA16816(acc[mi][1], a[mi], bf[2], bf[3]);
        }
        // Epilogue: window w = (nb + 8*nj)/4 + (t4>>1); pool = max over 4 quads
        int w0 = (nb >> 2) + (t4 >> 1);
        #pragma unroll
        for (int nj = 0; nj < 2; nj++) {
            int w = w0 + nj * 2;
            int py = w / 14, px = w % 14;
            size_t obase = (size_t)((py + 1) * 16 + px + 1) * 64;
            #pragma unroll
            for (int mi = 0; mi < 4; mi++)
                #pragma unroll
                for (int ro = 0; ro < 2; ro++) {
                    float v0 = al[mi][ro] * acc[mi][nj][2 * ro]     + be[mi][ro];
                    float v1 = al[mi][ro] * acc[mi][nj][2 * ro + 1] + be[mi][ro];
                    float m2 = fmaxf(v0, v1);
                    float o  = __shfl_xor_sync(0xffffffffu, m2, 1);
                    float m4 = fmaxf(fmaxf(m2, o), 0.f);
                    if (!(t4 & 1))
                        ob[obase + mi * 16 + trow + ro * 8] = __float2bfloat16(m4);
                }
        }
    }
}

// ---------------------------------------------------------------------------
// conv2 HMMA (persistent): D[128oc x 256pos] per image, 9 shifts x K=64.
// XOR-swizzled 128B-pitch smem; weights resident; double-buffered act tiles.
// ---------------------------------------------------------------------------
#define C2_SW_BYTES (9 * 128 * 128)              // 147456
#define C2_SB_OFF   C2_SW_BYTES
#define C2_SB_BYTES (264 * 128)                  // 33792 per buffer
#define C2_SMEM     (C2_SW_BYTES + 2 * C2_SB_BYTES) // 215040

__global__ __launch_bounds__(512, 1) void conv2_mma()
{
    extern __shared__ char dsm[];
    uint32_t sb = smem_u32(dsm);
    int tid = threadIdx.x;
    int lane = tid & 31, warp = tid >> 5;
    int wm = warp & 3, wn = warp >> 2;
    int t4 = lane & 3, trow = lane >> 2;

    for (int i = tid; i < 9216; i += 512) {
        uint4 val = ((const uint4*)g_w2T)[i];
        int rl = i >> 3, q = i & 7;
        int s = rl >> 7, r = rl & 127;
        *(uint4*)(dsm + s * 16384 + r * 128 + ((q ^ (r & 7)) << 4)) = val;
    }

    float al[2][2], be[2][2];
    #pragma unroll
    for (int i = 0; i < 2; i++)
        #pragma unroll
        for (int ro = 0; ro < 2; ro++) {
            int oc = wm * 32 + i * 16 + trow + ro * 8;
            al[i][ro] = g_bn2[oc];
            be[i][ro] = g_bn2[128 + oc];
        }

    int npairs = (wn == 3) ? 2 : 4;

    int img0 = blockIdx.x;
    if (img0 < B_IMG) {
        const char* src = (const char*)(g_act1 + (size_t)img0 * 256 * 64);
        for (int i = tid; i < 2112; i += 512) {
            int r = i >> 3, q = i & 7;
            CP16(sb + C2_SB_OFF + r * 128 + ((q ^ (r & 7)) << 4), src + i * 16);
        }
    }
    CP_COMMIT();
    __syncthreads();

    int pb = 0;
    for (int img = img0; img < B_IMG; img += gridDim.x) {
        CP_WAIT0();
        __syncthreads();

        int nxt = img + gridDim.x;
        if (nxt < B_IMG) {
            const char* src = (const char*)(g_act1 + (size_t)nxt * 256 * 64);
            uint32_t dstb = sb + C2_SB_OFF + (pb ^ 1) * C2_SB_BYTES;
            for (int i = tid; i < 2112; i += 512) {
                int r = i >> 3, q = i & 7;
                CP16(dstb + r * 128 + ((q ^ (r & 7)) << 4), src + i * 16);
            }
        }
        CP_COMMIT();

        float acc[2][8][4];
        #pragma unroll
        for (int i = 0; i < 2; i++)
            #pragma unroll
            for (int j = 0; j < 8; j++)
                #pragma unroll
                for (int k = 0; k < 4; k++) acc[i][j][k] = 0.f;

        uint32_t actb = sb + C2_SB_OFF + pb * C2_SB_BYTES;
        #pragma unroll 1
        for (int s = 0; s < 9; s++) {
            int shift = (s / 3) * 16 + (s % 3);
            uint32_t aB = sb + s * 16384;
            #pragma unroll
            for (int kt = 0; kt < 4; kt++) {
                int ua = kt * 2 + ((lane >> 4) & 1);
                int ub = kt * 2 + ((lane >> 3) & 1);
                uint32_t a[2][4];
                #pragma unroll
                for (int i = 0; i < 2; i++) {
                    int r = wm * 32 + i * 16 + (lane & 15);
                    LDSM_X4(a[i], aB + r * 128 + ((ua ^ (r & 7)) << 4));
                }
                #pragma unroll
                for (int jp = 0; jp < 4; jp++) {
                    if (jp < npairs) {
                        uint32_t r4[4];
                        int r = shift + wn * 64 + jp * 16 + ((lane & 16) >> 1) + (lane & 7);
                        LDSM_X4(r4, actb + r * 128 + ((ub ^ (r & 7)) << 4));
                        #pragma unroll
                        for (int i = 0; i < 2; i++) {
                            MMA16816(acc[i][2 * jp],     a[i], r4[0], r4[1]);
                            MMA16816(acc[i][2 * jp + 1], a[i], r4[2], r4[3]);
                        }
                    }
                }
            }
        }

        #pragma unroll
        for (int i = 0; i < 2; i++)
            #pragma unroll
            for (int jj = 0; jj < 4; jj++) {
                int j = (jj < 2) ? jj : jj + 2;   // {0,1,4,5}
                int n0 = wn * 64 + j * 8 + 2 * t4;
                int p = n0 + 17;
                int r = p >> 4, c = p & 15;
                if ((r & 1) && r < 15 && (c & 1) && c < 15) {
                    #pragma unroll
                    for (int ro = 0; ro < 2; ro++) {
                        float a = al[i][ro], bt = be[i][ro];
                        float v0 = a * acc[i][j][2 * ro] + bt;
                        float v1 = a * acc[i][j][2 * ro + 1] + bt;
                        float v2 = a * acc[i][j + 2][2 * ro] + bt;
                        float v3 = a * acc[i][j + 2][2 * ro + 1] + bt;
                        float mx = fmaxf(fmaxf(fmaxf(v0, v1), fmaxf(v2, v3)), 0.f);
                        int oc = wm * 32 + i * 16 + trow + ro * 8;
                        int py = (r - 1) >> 1, px = (c - 1) >> 1;
                        g_act2[(size_t)(oc >> 6) * PLANE_ELEMS +
                               ((size_t)img * 64 + (py + 1) * 8 + px + 1) * 64 + (oc & 63)]
                            = __float2bfloat16(mx);
                    }
                }
            }
        pb ^= 1;
    }
}

// ---------------------------------------------------------------------------
// conv3 HMMA: 256 threads, 2 images x 128 oc per CTA, 2 CTAs/SM.
// wm-group-shared 3-deep cp.async A ring + 64-thread named barriers.
// ---------------------------------------------------------------------------
#define C3_B_WIN   9504                           // 66 rows * 144B
#define C3_A_OFF   (4 * C3_B_WIN)                 // 38016
#define C3_A_STAGE 4608                           // 32 rows * 144B
#define C3_SMEM    (C3_A_OFF + 4 * 3 * C3_A_STAGE) // 93312

__global__ __launch_bounds__(256, 2) void conv3_mma()
{
    extern __shared__ char dsm[];
    uint32_t sb = smem_u32(dsm);
    int tid = threadIdx.x;
    int lane = tid & 31, warp = tid >> 5;
    int wm = warp & 3, wn = warp >> 2;
    int t4 = lane & 3, trow = lane >> 2;
    int grp2 = blockIdx.x, half = blockIdx.y;
    int gi = wn * 32 + lane;

    auto prefA = [&](int st) {
        uint32_t dst0 = sb + C3_A_OFF + (uint32_t)(wm * 3 + (st % 3)) * C3_A_STAGE;
        #pragma unroll
        for (int u = 0; u < 4; u++) {
            int idx = gi + u * 64;
            int row = idx >> 3, q = idx & 7;
            const char* src = (const char*)g_w3T +
                (((size_t)st * 256 + half * 128 + wm * 32 + row) * 64 + q * 8) * 2;
            CP16(dst0 + row * 144 + q * 16, src);
        }
    };

    for (int i = tid; i < 2112; i += 256) {
        int w = i / 528, rem = i - w * 528;
        int row = rem >> 3, q = rem & 7;
        int img = w >> 1, pl = w & 1;
        const char* src = (const char*)(g_act2 + (size_t)pl * PLANE_ELEMS +
                          ((size_t)(grp2 * 2 + img) * 64 + row) * 64 + q * 8);
        CP16(sb + (uint32_t)w * C3_B_WIN + row * 144 + q * 16, src);
    }
    prefA(0);
    CP_COMMIT();
    prefA(1);
    CP_COMMIT();
    CP_WAIT1();
    __syncthreads();

    float acc[2][6][4];
    #pragma unroll
    for (int i = 0; i < 2; i++)
        #pragma unroll
        for (int j = 0; j < 6; j++)
            #pragma unroll
            for (int k = 0; k < 4; k++) acc[i][j][k] = 0.f;

    #pragma unroll 1
    for (int st = 0; st < 18; st++) {
        if (st + 2 < 18) prefA(st + 2);
        CP_COMMIT();

        int s9 = st >> 1, h = st & 1;
        int shift = (s9 / 3) * 8 + (s9 % 3);
        uint32_t aB = sb + C3_A_OFF + (uint32_t)(wm * 3 + (st % 3)) * C3_A_STAGE;
        uint32_t bB = sb + (uint32_t)(wn * 2 + h) * C3_B_WIN + shift * 144;
        #pragma unroll
        for (int kt = 0; kt < 4; kt++) {
            uint32_t a[2][4];
            #pragma unroll
            for (int i = 0; i < 2; i++) {
                uint32_t addr = aB + (i * 16 + (lane & 15)) * 144 + ((lane >> 4) & 1) * 16 + kt * 32;
                LDSM_X4(a[i], addr);
            }
            #pragma unroll
            for (int jp = 0; jp < 3; jp++) {
                uint32_t r[4];
                uint32_t addr = bB + (jp * 16 + ((lane & 16) >> 1) + (lane & 7)) * 144
                                + kt * 32 + ((lane >> 3) & 1) * 16;
                LDSM_X4(r, addr);
                #pragma unroll
                for (int i = 0; i < 2; i++) {
                    MMA16816(acc[i][2 * jp],     a[i], r[0], r[1]);
                    MMA16816(acc[i][2 * jp + 1], a[i], r[2], r[3]);
                }
            }
        }
        CP_WAIT1();
        BAR_GRP(1 + wm, 64);
    }

    int img = grp2 * 2 + wn;
    #pragma unroll
    for (int i = 0; i < 2; i++)
        #pragma unroll
        for (int ro = 0; ro < 2; ro++) {
            int ch = half * 128 + wm * 32 + i * 16 + trow + ro * 8;
            float a = g_bn3[ch];
            float bt = g_bn3[256 + ch];
            if (t4 < 3) {
                #pragma unroll
                for (int jh = 0; jh < 3; jh++) {
                    int j = 2 * jh;
                    float v0 = a * acc[i][j][2 * ro] + bt;
                    float v1 = a * acc[i][j][2 * ro + 1] + bt;
                    float v2 = a * acc[i][j + 1][2 * ro] + bt;
                    float v3 = a * acc[i][j + 1][2 * ro + 1] + bt;
                    float mx = fmaxf(fmaxf(fmaxf(v0, v1), fmaxf(v2, v3)), 0.f);
                    g_buf3[(size_t)img * 2304 + ch * 9 + jh * 3 + t4] = mx;
                }
            }
        }
}

// ---------------------------------------------------------------------------
// Tail: analytic quantum collapse + fc chain + log_softmax. 1 warp / image.
// ---------------------------------------------------------------------------
__global__ __launch_bounds__(256) void tail_kernel(
    const float* __restrict__ fc1_w, const float* __restrict__ fc1_b,
    const float* __restrict__ qp,
    const float* __restrict__ fc2_w, const float* __restrict__ fc2_b,
    const float* __restrict__ fc3_w, const float* __restrict__ fc3_b,
    float* __restrict__ out)
{
    __shared__ float sAC[4];
    int tid = threadIdx.x;
    if (tid == 0) {
        float a0 = 0.f, a1 = 0.f, c0 = 0.f, c1 = 0.f;
        for (int j = 0; j < 128; j++) {
            float f2 = fc2_w[j], f2b = fc2_b[j];
            a0 += fc3_w[j] * f2;       a1 += fc3_w[128 + j] * f2;
            c0 += fc3_w[j] * f2b;      c1 += fc3_w[128 + j] * f2b;
        }
        sAC[0] = a0; sAC[1] = a1;
        sAC[2] = c0 + fc3_b[0]; sAC[3] = c1 + fc3_b[1];
    }
    __syncthreads();

    int warp = tid >> 5, lane = tid & 31;
    int b = blockIdx.x * 8 + warp;
    const float* p3 = g_buf3 + (size_t)b * 2304;
    const float* w1 = fc1_w + 2304;
    float s = 0.f;
    for (int i = lane; i < 2304; i += 32) s += p3[i] * w1[i];
    #pragma unroll
    for (int o = 16; o; o >>= 1) s += __shfl_xor_sync(0xffffffffu, s, o);
    if (lane == 0) {
        s += fc1_b[1];
        float q = cosf(s) * cosf(qp[1]);
        float l0 = q * sAC[0] + sAC[2];
        float l1 = q * sAC[1] + sAC[3];
        float mx = fmaxf(l0, l1);
        float lse = mx + logf(expf(l0 - mx) + expf(l1 - mx));
        out[(size_t)b * 2]     = l0 - lse;
        out[(size_t)b * 2 + 1] = l1 - lse;
    }
}

// ---------------------------------------------------------------------------
extern "C" void kernel_launch(void* const* d_in, const int* in_sizes, int n_in,
                              void* d_out, int out_size)
{
    const float* x    = (const float*)d_in[0];
    const float* c1w  = (const float*)d_in[1];
    const float* c1b  = (const float*)d_in[2];
    const float* c2w  = (const float*)d_in[3];
    const float* c2b  = (const float*)d_in[4];
    const float* c3w  = (const float*)d_in[5];
    const float* c3b  = (const float*)d_in[6];
    const float* bn1g = (const float*)d_in[7];
    const float* bn1b = (const float*)d_in[8];
    const float* bn1m = (const float*)d_in[9];
    const float* bn1v = (const float*)d_in[10];
    const float* bn2g = (const float*)d_in[11];
    const float* bn2b = (const float*)d_in[12];
    const float* bn2m = (const float*)d_in[13];
    const float* bn2v = (const float*)d_in[14];
    const float* bn3g = (const float*)d_in[15];
    const float* bn3b = (const float*)d_in[16];
    const float* bn3m = (const float*)d_in[17];
    const float* bn3v = (const float*)d_in[18];
    const float* fc1w = (const float*)d_in[19];
    const float* fc1b = (const float*)d_in[20];
    const float* qpar = (const float*)d_in[21];
    const float* fc2w = (const float*)d_in[22];
    const float* fc2b = (const float*)d_in[23];
    const float* fc3w = (const float*)d_in[24];
    const float* fc3b = (const float*)d_in[25];
    float* out = (float*)d_out;

    cudaFuncSetAttribute(conv2_mma, cudaFuncAttributeMaxDynamicSharedMemorySize, C2_SMEM);
    cudaFuncSetAttribute(conv3_mma, cudaFuncAttributeMaxDynamicSharedMemorySize, C3_SMEM);

    wtrans_kernel<<<(18 * 256 * 64 + 255) / 256, 256>>>(
        c1w, c2w, c3w,
        c1b, bn1g, bn1b, bn1m, bn1v,
        c2b, bn2g, bn2b, bn2m, bn2v,
        c3b, bn3g, bn3b, bn3m, bn3v);
    conv1_mma<<<B_IMG, 256>>>(x);
    conv2_mma<<<592, 512, C2_SMEM>>>();
    conv3_mma<<<dim3(B_IMG / 2, 2), 256, C3_SMEM>>>();
    tail_kernel<<<B_IMG / 8, 256>>>(fc1w, fc1b, qpar, fc2w, fc2b, fc3w, fc3b, out);
}